// round 9
// baseline (speedup 1.0000x reference)
#include <cuda_runtime.h>

// BallPredictorGNN — ONE fused kernel, sparse dependency cone + linear GAT.
// NB = 4 blocks/SM, co-residency guaranteed by __launch_bounds__(256,4),
// so software grid barriers are safe. Barrier waiters poll with VOLATILE
// L2 reads (atomic only to arrive) — atomic polling from 592 blocks
// saturates the L2 atomic unit and stalls the arrivals themselves.
// Phases:
//  P1: blocks 0-7 prep was/wad = W1 @ a_{src,dst}1 ; blocks 8+ scan dst==ball
//  P2: all blocks scan edges whose dst is in need1 -> compact edge list
//  P3: blocks 0..n1-1: per-node softmax over in-edges, aggregate x, @W1,
//      relu, @W2 -> g2, layer-2 logits
//  P4: last-done block: layer-2 softmax at ball, aggregate g2, MLP -> out[2],
//      then reset all device state for the next graph replay.

#define NMAX      20480
#define FIN       128
#define H1C       256
#define C2        64
#define SRCA_CAP  1024
#define EB_CAP    65536
#define LIST_CAP  4096
#define DEG_CAP   512

__device__ int   g_need1[NMAX];          // reset via list at end of each call
__device__ int   g_cntA, g_cntB, g_cnt1, g_done;
__device__ int   g_barc[2];
__device__ int   g_srcA[SRCA_CAP];
__device__ int   g_srcB[EB_CAP];
__device__ int   g_dstB[EB_CAP];
__device__ int   g_list1[LIST_CAP];
__device__ float g_was[FIN * 4];         // [f*4+h]
__device__ float g_wad[FIN * 4];
__device__ float g_g2[(size_t)NMAX * C2];
__device__ float g_as2[NMAX], g_ad2[NMAX];

__device__ __forceinline__ void mark_need1(int v) {
    if (atomicExch(&g_need1[v], 1) == 0) {
        int p = atomicAdd(&g_cnt1, 1);
        if (p < LIST_CAP) g_list1[p] = v;
    }
}

// arrive with atomic, wait with volatile loads, acquire-fence on exit
__device__ __forceinline__ void gbar(int ph, int nb) {
    __syncthreads();
    if (threadIdx.x == 0) {
        __threadfence();                           // release
        atomicAdd(&g_barc[ph], 1);
        while (*(volatile int*)&g_barc[ph] < nb) __nanosleep(256);
        __threadfence();                           // acquire
    }
    __syncthreads();
}

__global__ void __launch_bounds__(256, 4)
fused_gnn(const float* __restrict__ x, const int* __restrict__ ei,
          const float* __restrict__ W1, const float* __restrict__ a_src1,
          const float* __restrict__ a_dst1, const float* __restrict__ b1,
          const float* __restrict__ W2, const float* __restrict__ a_src2,
          const float* __restrict__ a_dst2, const float* __restrict__ b2,
          const float* __restrict__ fc1_w, const float* __restrict__ fc1_b,
          const float* __restrict__ fc2_w, const float* __restrict__ fc2_b,
          float* __restrict__ out, int N, int E, int ball) {
    const int b = blockIdx.x, t = threadIdx.x, NB = gridDim.x;
    const int w = t >> 5, l = t & 31;

    // agg-phase shared
    __shared__ float s_was[FIN * 4];
    __shared__ float s_wad[FIN * 4];
    __shared__ int   s_src[DEG_CAP];
    __shared__ float s_e[DEG_CAP * 4];
    __shared__ float s_xv[FIN];
    __shared__ float s_xagg[4 * FIN];
    __shared__ float s_r1[H1C];
    __shared__ float s_part[4 * C2];
    __shared__ float s_g2[C2];
    __shared__ float s_adv[4];
    __shared__ float s_inv[4];
    __shared__ int   s_cnt;
    // final-phase shared
    __shared__ int   s_idx[SRCA_CAP + 1];
    __shared__ float sw[SRCA_CAP + 1];
    __shared__ float s_fc1[C2 * 32];
    __shared__ float s_o[C2];
    __shared__ float s_p2[8 * 32];
    __shared__ float s_z[32];
    __shared__ float s_red[16];
    __shared__ int   s_last;

    const int nq = (E + 3) >> 2;
    const int* dcol = ei + E;

    // ================= P1: prep (blocks 0-7) || scan1 (blocks 8+) =========
    if (b == 0 && t == 0) mark_need1(ball);
    if (b < 8) {
        int h = t >> 6, c = t & 63;
        float as = a_src1[h * 64 + c], ad = a_dst1[h * 64 + c];
        for (int f = b * 16; f < b * 16 + 16; f++) {
            float wv = W1[f * H1C + t];
            float ps = wv * as, pd = wv * ad;
#pragma unroll
            for (int o = 16; o; o >>= 1) {
                ps += __shfl_down_sync(~0u, ps, o);
                pd += __shfl_down_sync(~0u, pd, o);
            }
            if (l == 0) { s_red[w] = ps; s_red[8 + w] = pd; }
            __syncthreads();
            if (t < 4) {
                g_was[f * 4 + t] = s_red[2 * t] + s_red[2 * t + 1];
                g_wad[f * 4 + t] = s_red[8 + 2 * t] + s_red[8 + 2 * t + 1];
            }
            __syncthreads();
        }
    } else {
        const int nscan = (NB - 8) * 256;
        for (int q = (b - 8) * 256 + t; q < nq; q += nscan) {
            int base = q * 4;
            int d[4];
            if (base + 4 <= E) {
                int4 v4 = *reinterpret_cast<const int4*>(dcol + base);
                d[0] = v4.x; d[1] = v4.y; d[2] = v4.z; d[3] = v4.w;
            } else {
                for (int k = 0; k < 4; k++) d[k] = (base + k < E) ? dcol[base + k] : -1;
            }
#pragma unroll
            for (int k = 0; k < 4; k++) {
                if (d[k] == ball) {
                    int src = ei[base + k];
                    if ((unsigned)src >= (unsigned)N) continue;
                    int p = atomicAdd(&g_cntA, 1);
                    if (p < SRCA_CAP) g_srcA[p] = src;
                    mark_need1(src);
                }
            }
        }
    }
    gbar(0, NB);

    // ================= P2: scan2 (all blocks) =============================
    for (int q = b * 256 + t; q < nq; q += NB * 256) {
        int base = q * 4;
        int d[4];
        if (base + 4 <= E) {
            int4 v4 = *reinterpret_cast<const int4*>(dcol + base);
            d[0] = v4.x; d[1] = v4.y; d[2] = v4.z; d[3] = v4.w;
        } else {
            for (int k = 0; k < 4; k++) d[k] = (base + k < E) ? dcol[base + k] : -1;
        }
#pragma unroll
        for (int k = 0; k < 4; k++) {
            int dst = d[k];
            if ((unsigned)dst >= (unsigned)N) continue;
            if (g_need1[dst]) {
                int src = ei[base + k];
                if ((unsigned)src >= (unsigned)N) continue;
                int p = atomicAdd(&g_cntB, 1);
                if (p < EB_CAP) { g_srcB[p] = src; g_dstB[p] = dst; }
            }
        }
    }
    gbar(1, NB);

    // ================= P3: per-need1-node aggregate + project =============
    const int n1 = min(g_cnt1, LIST_CAP);
    const int cb = min(g_cntB, EB_CAP);
    if (b < n1) {
        for (int i = t; i < FIN * 4; i += 256) { s_was[i] = g_was[i]; s_wad[i] = g_wad[i]; }
        for (int it = b; it < n1; it += NB) {
            int v = g_list1[it];
            if (t == 0) s_cnt = 0;
            if (t < FIN) s_xv[t] = x[(size_t)v * FIN + t];
            __syncthreads();
            for (int j = t; j < cb; j += 256) {
                if (g_dstB[j] == v) {
                    int p = atomicAdd(&s_cnt, 1);
                    if (p < DEG_CAP - 1) s_src[p] = g_srcB[j];
                }
            }
            __syncthreads();
            if (t == 0) {
                int p = min(s_cnt, DEG_CAP - 1);
                s_src[p] = v;                 // appended self-loop
                s_cnt = p + 1;
            }
            if (w < 4) {                      // dst logits: x[v] . wad[:,h]
                float p = 0.f;
                for (int f = l; f < FIN; f += 32) p += s_xv[f] * s_wad[f * 4 + w];
#pragma unroll
                for (int o = 16; o; o >>= 1) p += __shfl_down_sync(~0u, p, o);
                if (l == 0) s_adv[w] = p;
            }
            __syncthreads();
            const int n = s_cnt;
            for (int j = w; j < n; j += 8) {  // src logits, warp per edge
                const float4 xv4 = reinterpret_cast<const float4*>(
                                       x + (size_t)s_src[j] * FIN)[l];
                float ph0 = 0.f, ph1 = 0.f, ph2 = 0.f, ph3 = 0.f;
                const float xs[4] = {xv4.x, xv4.y, xv4.z, xv4.w};
#pragma unroll
                for (int k = 0; k < 4; k++) {
                    int f = 4 * l + k;
                    ph0 += xs[k] * s_was[f * 4 + 0];
                    ph1 += xs[k] * s_was[f * 4 + 1];
                    ph2 += xs[k] * s_was[f * 4 + 2];
                    ph3 += xs[k] * s_was[f * 4 + 3];
                }
#pragma unroll
                for (int o = 16; o; o >>= 1) {
                    ph0 += __shfl_down_sync(~0u, ph0, o);
                    ph1 += __shfl_down_sync(~0u, ph1, o);
                    ph2 += __shfl_down_sync(~0u, ph2, o);
                    ph3 += __shfl_down_sync(~0u, ph3, o);
                }
                if (l == 0) {
                    float e0 = ph0 + s_adv[0], e1 = ph1 + s_adv[1];
                    float e2 = ph2 + s_adv[2], e3 = ph3 + s_adv[3];
                    s_e[j * 4 + 0] = (e0 > 0.f) ? e0 : 0.2f * e0;  // leaky_relu
                    s_e[j * 4 + 1] = (e1 > 0.f) ? e1 : 0.2f * e1;
                    s_e[j * 4 + 2] = (e2 > 0.f) ? e2 : 0.2f * e2;
                    s_e[j * 4 + 3] = (e3 > 0.f) ? e3 : 0.2f * e3;
                }
            }
            __syncthreads();
            if (t < 4) {                      // stable softmax per head
                float m = -1e30f;
                for (int j = 0; j < n; j++) m = fmaxf(m, s_e[j * 4 + t]);
                float s = 0.f;
                for (int j = 0; j < n; j++) {
                    float ww = expf(s_e[j * 4 + t] - m);
                    s_e[j * 4 + t] = ww; s += ww;
                }
                s_inv[t] = 1.f / (s + 1e-16f);
            }
            __syncthreads();
            if (t < FIN) {                    // xagg, 4-way unrolled gather
                float a0 = 0.f, a1 = 0.f, a2 = 0.f, a3 = 0.f;
                int j = 0;
                for (; j + 4 <= n; j += 4) {
                    float x0 = x[(size_t)s_src[j + 0] * FIN + t];
                    float x1 = x[(size_t)s_src[j + 1] * FIN + t];
                    float x2 = x[(size_t)s_src[j + 2] * FIN + t];
                    float x3 = x[(size_t)s_src[j + 3] * FIN + t];
                    a0 += s_e[(j+0)*4+0]*x0 + s_e[(j+1)*4+0]*x1 + s_e[(j+2)*4+0]*x2 + s_e[(j+3)*4+0]*x3;
                    a1 += s_e[(j+0)*4+1]*x0 + s_e[(j+1)*4+1]*x1 + s_e[(j+2)*4+1]*x2 + s_e[(j+3)*4+1]*x3;
                    a2 += s_e[(j+0)*4+2]*x0 + s_e[(j+1)*4+2]*x1 + s_e[(j+2)*4+2]*x2 + s_e[(j+3)*4+2]*x3;
                    a3 += s_e[(j+0)*4+3]*x0 + s_e[(j+1)*4+3]*x1 + s_e[(j+2)*4+3]*x2 + s_e[(j+3)*4+3]*x3;
                }
                for (; j < n; j++) {
                    float xv = x[(size_t)s_src[j] * FIN + t];
                    a0 += s_e[j*4+0]*xv; a1 += s_e[j*4+1]*xv;
                    a2 += s_e[j*4+2]*xv; a3 += s_e[j*4+3]*xv;
                }
                s_xagg[0 * FIN + t] = a0 * s_inv[0];
                s_xagg[1 * FIN + t] = a1 * s_inv[1];
                s_xagg[2 * FIN + t] = a2 * s_inv[2];
                s_xagg[3 * FIN + t] = a3 * s_inv[3];
            }
            __syncthreads();
            {                                 // @W1 -> r1
                const int h = t >> 6;
                float acc = 0.f;
#pragma unroll 8
                for (int f = 0; f < FIN; f++)
                    acc += s_xagg[h * FIN + f] * W1[f * H1C + t];
                s_r1[t] = fmaxf(acc + b1[t], 0.f);
            }
            __syncthreads();
            {                                 // g2 = r1 @ W2
                const int c = t & 63, q = t >> 6;
                float p = 0.f;
#pragma unroll 16
                for (int k = q * 64; k < q * 64 + 64; k++)
                    p += s_r1[k] * W2[k * C2 + c];
                s_part[q * C2 + c] = p;
            }
            __syncthreads();
            if (t < C2) {
                float g = s_part[t] + s_part[C2 + t] + s_part[2 * C2 + t] + s_part[3 * C2 + t];
                s_g2[t] = g;
                g_g2[(size_t)v * C2 + t] = g;
            }
            __syncthreads();
            if (w < 2) {                      // layer-2 logits: g2 . a_{src,dst}2
                const float* av = w ? a_dst2 : a_src2;
                float p = s_g2[l] * av[l] + s_g2[l + 32] * av[l + 32];
#pragma unroll
                for (int o = 16; o; o >>= 1) p += __shfl_down_sync(~0u, p, o);
                if (l == 0) { if (w) g_ad2[v] = p; else g_as2[v] = p; }
            }
            __syncthreads();
        }
    }

    // ================= done counter: last block does the final ============
    __syncthreads();
    if (t == 0) {
        __threadfence();
        s_last = (atomicAdd(&g_done, 1) + 1 == NB) ? 1 : 0;
        if (s_last) __threadfence();           // acquire before reading g2/as2
    }
    __syncthreads();
    if (!s_last) return;

    // ================= P4: final (one block) ==============================
    const int nA = min(g_cntA, SRCA_CAP);
    const int cnt = nA + 1;
    for (int j = t; j < cnt; j += 256) s_idx[j] = (j < nA) ? g_srcA[j] : ball;
    for (int i = t; i < C2 * 32; i += 256) s_fc1[i] = fc1_w[i];   // prefetch
    __syncthreads();
    const float adv = g_ad2[ball];
    for (int j = t; j < cnt; j += 256) {
        float e = g_as2[s_idx[j]] + adv;
        sw[j] = (e > 0.f) ? e : 0.2f * e;
    }
    __syncthreads();
    float lm = -1e30f;
    for (int j = t; j < cnt; j += 256) lm = fmaxf(lm, sw[j]);
#pragma unroll
    for (int o = 16; o; o >>= 1) lm = fmaxf(lm, __shfl_down_sync(~0u, lm, o));
    if (l == 0) s_red[w] = lm;
    __syncthreads();
    if (t < 8) {
        float v = s_red[t];
#pragma unroll
        for (int o = 4; o; o >>= 1) v = fmaxf(v, __shfl_down_sync(0xffu, v, o));
        if (t == 0) s_red[0] = v;
    }
    __syncthreads();
    const float m = s_red[0];
    float ls = 0.f;
    for (int j = t; j < cnt; j += 256) { float ww = expf(sw[j] - m); sw[j] = ww; ls += ww; }
#pragma unroll
    for (int o = 16; o; o >>= 1) ls += __shfl_down_sync(~0u, ls, o);
    if (l == 0) s_red[8 + w] = ls;
    __syncthreads();
    if (t < 8) {
        float v = s_red[8 + t];
#pragma unroll
        for (int o = 4; o; o >>= 1) v += __shfl_down_sync(0xffu, v, o);
        if (t == 0) s_red[8] = v;
    }
    __syncthreads();
    const float sinv = 1.f / (s_red[8] + 1e-16f);
    {   // aggregate g2: 4 j-chunks x 64 cols
        const int c = t & 63, q = t >> 6;
        float acc = 0.f;
        for (int j = q; j < cnt; j += 4)
            acc += sw[j] * g_g2[(size_t)s_idx[j] * C2 + c];
        s_part[q * C2 + c] = acc;
    }
    __syncthreads();
    if (t < C2) {
        float o = (s_part[t] + s_part[C2 + t] + s_part[2 * C2 + t] + s_part[3 * C2 + t])
                  * sinv + b2[t];
        s_o[t] = fmaxf(o, 0.f);
    }
    __syncthreads();
    {   // fc1 (weights in smem): 8 k-chunks x 32 outputs
        const int o = t & 31, q = t >> 5;
        float p = 0.f;
#pragma unroll
        for (int k = q * 8; k < q * 8 + 8; k++) p += s_o[k] * s_fc1[k * 32 + o];
        s_p2[q * 32 + o] = p;
    }
    __syncthreads();
    if (t < 32) {
        float a = fc1_b[t];
#pragma unroll
        for (int q = 0; q < 8; q++) a += s_p2[q * 32 + t];
        s_z[t] = fmaxf(a, 0.f);
    }
    __syncthreads();
    if (t < 2) {
        float a = fc2_b[t];
        for (int k = 0; k < 32; k++) a += s_z[k] * fc2_w[k * 2 + t];
        out[t] = a;
    }
    // ================= reset state for next graph replay ==================
    __syncthreads();
    const int n1r = min(g_cnt1, LIST_CAP);
    for (int i = t; i < n1r; i += 256) g_need1[g_list1[i]] = 0;
    if (t == 0) {
        g_cntA = 0; g_cntB = 0; g_cnt1 = 0; g_done = 0;
        g_barc[0] = 0; g_barc[1] = 0;
    }
}

extern "C" void kernel_launch(void* const* d_in, const int* in_sizes, int n_in,
                              void* d_out, int out_size) {
    const float* x      = (const float*)d_in[0];
    const int*   ei     = (const int*)d_in[1];   // int32 (JAX x64-disabled)
    const float* W1     = (const float*)d_in[2];
    const float* a_src1 = (const float*)d_in[3];
    const float* a_dst1 = (const float*)d_in[4];
    const float* b1     = (const float*)d_in[5];
    const float* W2     = (const float*)d_in[6];
    const float* a_src2 = (const float*)d_in[7];
    const float* a_dst2 = (const float*)d_in[8];
    const float* b2     = (const float*)d_in[9];
    const float* fc1_w  = (const float*)d_in[10];
    const float* fc1_b  = (const float*)d_in[11];
    const float* fc2_w  = (const float*)d_in[12];
    const float* fc2_b  = (const float*)d_in[13];

    int N = in_sizes[0] / FIN;   // 20000
    int E = in_sizes[1] / 2;     // 640000
    int ball = N - 1;

    int nsm = 148;
    cudaDeviceGetAttribute(&nsm, cudaDevAttrMultiProcessorCount, 0);
    int NB = nsm * 4;            // co-resident per __launch_bounds__(256,4)

    fused_gnn<<<NB, 256>>>(x, ei, W1, a_src1, a_dst1, b1, W2, a_src2, a_dst2,
                           b2, fc1_w, fc1_b, fc2_w, fc2_b, (float*)d_out,
                           N, E, ball);
}

// round 10
// speedup vs baseline: 1.0368x; 1.0368x over previous
#include <cuda_runtime.h>

// BallPredictorGNN — sparse dependency cone + linear-GAT factorization.
// 3 kernels: pass1(+was/wad prep) -> pass2 -> agg1(+final via done-counter).
// State (need1/counters) is reset by the final block each call; static
// zero-init covers the first call. No memset node.

#define NMAX      20480
#define FIN       128
#define H1C       256
#define C2        64
#define SRCA_CAP  1024
#define EB_CAP    65536
#define LIST_CAP  4096
#define DEG_CAP   512
#define AGG_GRID  64

__device__ int   g_need1[NMAX];          // reset via list at end of each call
__device__ int   g_cntA, g_cntB, g_cnt1, g_done;
__device__ int   g_srcA[SRCA_CAP];
__device__ int   g_srcB[EB_CAP];
__device__ int   g_dstB[EB_CAP];
__device__ int   g_list1[LIST_CAP];
__device__ float g_was[FIN * 4];         // [f*4+h]
__device__ float g_wad[FIN * 4];
__device__ float g_g2[(size_t)NMAX * C2];
__device__ float g_as2[NMAX], g_ad2[NMAX];

__device__ __forceinline__ void mark_need1(int v) {
    if (atomicExch(&g_need1[v], 1) == 0) {
        int p = atomicAdd(&g_cnt1, 1);
        if (p < LIST_CAP) g_list1[p] = v;
    }
}

// blocks 0-7: was/wad prep; blocks 8+: scan dst column for edges into ball
__global__ void k_pass1(const int* __restrict__ ei, int E, int ball, int N,
                        const float* __restrict__ W1,
                        const float* __restrict__ a_src1, const float* __restrict__ a_dst1) {
    const int b = blockIdx.x, t = threadIdx.x;
    const int w = t >> 5, l = t & 31;
    if (b == 0 && t == 0) mark_need1(ball);
    if (b < 8) {
        __shared__ float s_red[16];
        int h = t >> 6, c = t & 63;
        float as = a_src1[h * 64 + c], ad = a_dst1[h * 64 + c];
        for (int f = b * 16; f < b * 16 + 16; f++) {
            float wv = W1[f * H1C + t];
            float ps = wv * as, pd = wv * ad;
#pragma unroll
            for (int o = 16; o; o >>= 1) {
                ps += __shfl_down_sync(~0u, ps, o);
                pd += __shfl_down_sync(~0u, pd, o);
            }
            if (l == 0) { s_red[w] = ps; s_red[8 + w] = pd; }
            __syncthreads();
            if (t < 4) {
                g_was[f * 4 + t] = s_red[2 * t] + s_red[2 * t + 1];
                g_wad[f * 4 + t] = s_red[8 + 2 * t] + s_red[8 + 2 * t + 1];
            }
            __syncthreads();
        }
        return;
    }
    const int nq = (E + 3) >> 2;
    const int* dcol = ei + E;
    const int nscan = (gridDim.x - 8) * 256;
    for (int q = (b - 8) * 256 + t; q < nq; q += nscan) {
        int base = q * 4;
        int d[4];
        if (base + 4 <= E) {
            int4 v4 = *reinterpret_cast<const int4*>(dcol + base);
            d[0] = v4.x; d[1] = v4.y; d[2] = v4.z; d[3] = v4.w;
        } else {
            for (int k = 0; k < 4; k++) d[k] = (base + k < E) ? dcol[base + k] : -1;
        }
#pragma unroll
        for (int k = 0; k < 4; k++) {
            if (d[k] == ball) {
                int src = ei[base + k];
                if ((unsigned)src >= (unsigned)N) continue;
                int p = atomicAdd(&g_cntA, 1);
                if (p < SRCA_CAP) g_srcA[p] = src;
                mark_need1(src);
            }
        }
    }
}

__global__ void k_pass2(const int* __restrict__ ei, int E, int N) {
    const int nq = (E + 3) >> 2;
    const int* dcol = ei + E;
    int q = blockIdx.x * blockDim.x + threadIdx.x;
    if (q >= nq) return;
    int base = q * 4;
    int d[4];
    if (base + 4 <= E) {
        int4 v4 = *reinterpret_cast<const int4*>(dcol + base);
        d[0] = v4.x; d[1] = v4.y; d[2] = v4.z; d[3] = v4.w;
    } else {
        for (int k = 0; k < 4; k++) d[k] = (base + k < E) ? dcol[base + k] : -1;
    }
#pragma unroll
    for (int k = 0; k < 4; k++) {
        int dst = d[k];
        if ((unsigned)dst >= (unsigned)N) continue;
        if (g_need1[dst]) {
            int src = ei[base + k];
            if ((unsigned)src >= (unsigned)N) continue;
            int p = atomicAdd(&g_cntB, 1);
            if (p < EB_CAP) { g_srcB[p] = src; g_dstB[p] = dst; }
        }
    }
}

// One block per need1 node; LAST finishing block also runs the final phase
// (layer-2 softmax at ball, aggregate g2, MLP -> out[2]) and resets state.
__global__ void k_agg1(const float* __restrict__ x, const float* __restrict__ W1,
                       const float* __restrict__ b1, const float* __restrict__ W2,
                       const float* __restrict__ a_src2, const float* __restrict__ a_dst2,
                       const float* __restrict__ b2,
                       const float* __restrict__ fc1_w, const float* __restrict__ fc1_b,
                       const float* __restrict__ fc2_w, const float* __restrict__ fc2_b,
                       float* __restrict__ out, int ball) {
    __shared__ float s_was[FIN * 4];
    __shared__ float s_wad[FIN * 4];
    __shared__ int   s_src[DEG_CAP];
    __shared__ float s_e[DEG_CAP * 4];
    __shared__ float s_xv[FIN];
    __shared__ float s_xagg[4 * FIN];
    __shared__ float s_r1[H1C];
    __shared__ float s_part[4 * C2];
    __shared__ float s_g2[C2];
    __shared__ float s_adv[4];
    __shared__ float s_inv[4];
    __shared__ int   s_cnt;
    __shared__ float s_fc1[C2 * 32];
    __shared__ int   s_idx[SRCA_CAP + 1];
    __shared__ float sw[SRCA_CAP + 1];
    __shared__ float s_o[C2];
    __shared__ float s_p2[8 * 32];
    __shared__ float s_z[32];
    __shared__ float s_red[16];
    __shared__ int   s_last;
    const int t = threadIdx.x, w = t >> 5, l = t & 31, b = blockIdx.x;
    const int n1 = min(g_cnt1, LIST_CAP);
    const int cb = min(g_cntB, EB_CAP);

    // prefetch fc1 weights in every block (so the final-runner has them hot)
    for (int i = t; i < C2 * 32; i += 256) s_fc1[i] = fc1_w[i];

    if (b < n1) {
        for (int i = t; i < FIN * 4; i += 256) { s_was[i] = g_was[i]; s_wad[i] = g_wad[i]; }
        for (int it = b; it < n1; it += AGG_GRID) {
            int v = g_list1[it];
            if (t == 0) s_cnt = 0;
            if (t < FIN) s_xv[t] = x[(size_t)v * FIN + t];
            __syncthreads();
            for (int j = t; j < cb; j += 256) {
                if (g_dstB[j] == v) {
                    int p = atomicAdd(&s_cnt, 1);
                    if (p < DEG_CAP - 1) s_src[p] = g_srcB[j];
                }
            }
            __syncthreads();
            if (t == 0) {
                int p = min(s_cnt, DEG_CAP - 1);
                s_src[p] = v;                 // appended self-loop
                s_cnt = p + 1;
            }
            if (w < 4) {                      // dst logits: x[v] . wad[:,h]
                float p = 0.f;
                for (int f = l; f < FIN; f += 32) p += s_xv[f] * s_wad[f * 4 + w];
#pragma unroll
                for (int o = 16; o; o >>= 1) p += __shfl_down_sync(~0u, p, o);
                if (l == 0) s_adv[w] = p;
            }
            __syncthreads();
            const int n = s_cnt;
            for (int j = w; j < n; j += 8) {  // src logits, warp per edge
                const float4 xv4 = reinterpret_cast<const float4*>(
                                       x + (size_t)s_src[j] * FIN)[l];
                float ph0 = 0.f, ph1 = 0.f, ph2 = 0.f, ph3 = 0.f;
                const float xs[4] = {xv4.x, xv4.y, xv4.z, xv4.w};
#pragma unroll
                for (int k = 0; k < 4; k++) {
                    int f = 4 * l + k;
                    ph0 += xs[k] * s_was[f * 4 + 0];
                    ph1 += xs[k] * s_was[f * 4 + 1];
                    ph2 += xs[k] * s_was[f * 4 + 2];
                    ph3 += xs[k] * s_was[f * 4 + 3];
                }
#pragma unroll
                for (int o = 16; o; o >>= 1) {
                    ph0 += __shfl_down_sync(~0u, ph0, o);
                    ph1 += __shfl_down_sync(~0u, ph1, o);
                    ph2 += __shfl_down_sync(~0u, ph2, o);
                    ph3 += __shfl_down_sync(~0u, ph3, o);
                }
                if (l == 0) {
                    float e0 = ph0 + s_adv[0], e1 = ph1 + s_adv[1];
                    float e2 = ph2 + s_adv[2], e3 = ph3 + s_adv[3];
                    s_e[j * 4 + 0] = (e0 > 0.f) ? e0 : 0.2f * e0;  // leaky_relu
                    s_e[j * 4 + 1] = (e1 > 0.f) ? e1 : 0.2f * e1;
                    s_e[j * 4 + 2] = (e2 > 0.f) ? e2 : 0.2f * e2;
                    s_e[j * 4 + 3] = (e3 > 0.f) ? e3 : 0.2f * e3;
                }
            }
            __syncthreads();
            if (t < 4) {                      // stable softmax per head
                float m = -1e30f;
                for (int j = 0; j < n; j++) m = fmaxf(m, s_e[j * 4 + t]);
                float s = 0.f;
                for (int j = 0; j < n; j++) {
                    float ww = expf(s_e[j * 4 + t] - m);
                    s_e[j * 4 + t] = ww; s += ww;
                }
                s_inv[t] = 1.f / (s + 1e-16f);
            }
            __syncthreads();
            if (t < FIN) {                    // xagg, 4-way unrolled gather
                float a0 = 0.f, a1 = 0.f, a2 = 0.f, a3 = 0.f;
                int j = 0;
                for (; j + 4 <= n; j += 4) {
                    float x0 = x[(size_t)s_src[j + 0] * FIN + t];
                    float x1 = x[(size_t)s_src[j + 1] * FIN + t];
                    float x2 = x[(size_t)s_src[j + 2] * FIN + t];
                    float x3 = x[(size_t)s_src[j + 3] * FIN + t];
                    a0 += s_e[(j+0)*4+0]*x0 + s_e[(j+1)*4+0]*x1 + s_e[(j+2)*4+0]*x2 + s_e[(j+3)*4+0]*x3;
                    a1 += s_e[(j+0)*4+1]*x0 + s_e[(j+1)*4+1]*x1 + s_e[(j+2)*4+1]*x2 + s_e[(j+3)*4+1]*x3;
                    a2 += s_e[(j+0)*4+2]*x0 + s_e[(j+1)*4+2]*x1 + s_e[(j+2)*4+2]*x2 + s_e[(j+3)*4+2]*x3;
                    a3 += s_e[(j+0)*4+3]*x0 + s_e[(j+1)*4+3]*x1 + s_e[(j+2)*4+3]*x2 + s_e[(j+3)*4+3]*x3;
                }
                for (; j < n; j++) {
                    float xv = x[(size_t)s_src[j] * FIN + t];
                    a0 += s_e[j*4+0]*xv; a1 += s_e[j*4+1]*xv;
                    a2 += s_e[j*4+2]*xv; a3 += s_e[j*4+3]*xv;
                }
                s_xagg[0 * FIN + t] = a0 * s_inv[0];
                s_xagg[1 * FIN + t] = a1 * s_inv[1];
                s_xagg[2 * FIN + t] = a2 * s_inv[2];
                s_xagg[3 * FIN + t] = a3 * s_inv[3];
            }
            __syncthreads();
            {                                 // @W1 -> r1
                const int h = t >> 6;
                float acc = 0.f;
#pragma unroll 8
                for (int f = 0; f < FIN; f++)
                    acc += s_xagg[h * FIN + f] * W1[f * H1C + t];
                s_r1[t] = fmaxf(acc + b1[t], 0.f);
            }
            __syncthreads();
            {                                 // g2 = r1 @ W2
                const int c = t & 63, q = t >> 6;
                float p = 0.f;
#pragma unroll 16
                for (int k = q * 64; k < q * 64 + 64; k++)
                    p += s_r1[k] * W2[k * C2 + c];
                s_part[q * C2 + c] = p;
            }
            __syncthreads();
            if (t < C2) {
                float g = s_part[t] + s_part[C2 + t] + s_part[2 * C2 + t] + s_part[3 * C2 + t];
                s_g2[t] = g;
                g_g2[(size_t)v * C2 + t] = g;
            }
            __syncthreads();
            if (w < 2) {                      // layer-2 logits: g2 . a_{src,dst}2
                const float* av = w ? a_dst2 : a_src2;
                float p = s_g2[l] * av[l] + s_g2[l + 32] * av[l + 32];
#pragma unroll
                for (int o = 16; o; o >>= 1) p += __shfl_down_sync(~0u, p, o);
                if (l == 0) { if (w) g_ad2[v] = p; else g_as2[v] = p; }
            }
            __syncthreads();
        }
    }

    // ---- done counter: last-finishing block runs the final phase ----
    __syncthreads();
    if (t == 0) {
        __threadfence();
        s_last = (atomicAdd(&g_done, 1) + 1 == gridDim.x) ? 1 : 0;
        if (s_last) __threadfence();          // acquire before reading g2/as2
    }
    __syncthreads();
    if (!s_last) return;

    // ================= final (one block) ==================================
    const int nA = min(g_cntA, SRCA_CAP);
    const int cnt = nA + 1;
    for (int j = t; j < cnt; j += 256) s_idx[j] = (j < nA) ? g_srcA[j] : ball;
    __syncthreads();
    const float adv = g_ad2[ball];
    for (int j = t; j < cnt; j += 256) {
        float e = g_as2[s_idx[j]] + adv;
        sw[j] = (e > 0.f) ? e : 0.2f * e;
    }
    __syncthreads();
    float lm = -1e30f;
    for (int j = t; j < cnt; j += 256) lm = fmaxf(lm, sw[j]);
#pragma unroll
    for (int o = 16; o; o >>= 1) lm = fmaxf(lm, __shfl_down_sync(~0u, lm, o));
    if (l == 0) s_red[w] = lm;
    __syncthreads();
    if (t < 8) {
        float v = s_red[t];
#pragma unroll
        for (int o = 4; o; o >>= 1) v = fmaxf(v, __shfl_down_sync(0xffu, v, o));
        if (t == 0) s_red[0] = v;
    }
    __syncthreads();
    const float m = s_red[0];
    float ls = 0.f;
    for (int j = t; j < cnt; j += 256) { float ww = expf(sw[j] - m); sw[j] = ww; ls += ww; }
#pragma unroll
    for (int o = 16; o; o >>= 1) ls += __shfl_down_sync(~0u, ls, o);
    if (l == 0) s_red[8 + w] = ls;
    __syncthreads();
    if (t < 8) {
        float v = s_red[8 + t];
#pragma unroll
        for (int o = 4; o; o >>= 1) v += __shfl_down_sync(0xffu, v, o);
        if (t == 0) s_red[8] = v;
    }
    __syncthreads();
    const float sinv = 1.f / (s_red[8] + 1e-16f);
    {   // aggregate g2: 4 j-chunks x 64 cols (rows L2-hot from agg phase)
        const int c = t & 63, q = t >> 6;
        float acc = 0.f;
        for (int j = q; j < cnt; j += 4)
            acc += sw[j] * g_g2[(size_t)s_idx[j] * C2 + c];
        s_part[q * C2 + c] = acc;
    }
    __syncthreads();
    if (t < C2) {
        float o = (s_part[t] + s_part[C2 + t] + s_part[2 * C2 + t] + s_part[3 * C2 + t])
                  * sinv + b2[t];
        s_o[t] = fmaxf(o, 0.f);
    }
    __syncthreads();
    {   // fc1 (weights in smem): 8 k-chunks x 32 outputs
        const int o = t & 31, q = t >> 5;
        float p = 0.f;
#pragma unroll
        for (int k = q * 8; k < q * 8 + 8; k++) p += s_o[k] * s_fc1[k * 32 + o];
        s_p2[q * 32 + o] = p;
    }
    __syncthreads();
    if (t < 32) {
        float a = fc1_b[t];
#pragma unroll
        for (int q = 0; q < 8; q++) a += s_p2[q * 32 + t];
        s_z[t] = fmaxf(a, 0.f);
    }
    __syncthreads();
    if (t < 2) {
        float a = fc2_b[t];
        for (int k = 0; k < 32; k++) a += s_z[k] * fc2_w[k * 2 + t];
        out[t] = a;
    }
    // ---- reset state for next graph replay ----
    __syncthreads();
    const int n1r = min(g_cnt1, LIST_CAP);
    for (int i = t; i < n1r; i += 256) g_need1[g_list1[i]] = 0;
    if (t == 0) { g_cntA = 0; g_cntB = 0; g_cnt1 = 0; g_done = 0; }
}

extern "C" void kernel_launch(void* const* d_in, const int* in_sizes, int n_in,
                              void* d_out, int out_size) {
    const float* x      = (const float*)d_in[0];
    const int*   ei     = (const int*)d_in[1];   // int32 (JAX x64-disabled)
    const float* W1     = (const float*)d_in[2];
    const float* a_src1 = (const float*)d_in[3];
    const float* a_dst1 = (const float*)d_in[4];
    const float* b1     = (const float*)d_in[5];
    const float* W2     = (const float*)d_in[6];
    const float* a_src2 = (const float*)d_in[7];
    const float* a_dst2 = (const float*)d_in[8];
    const float* b2     = (const float*)d_in[9];
    const float* fc1_w  = (const float*)d_in[10];
    const float* fc1_b  = (const float*)d_in[11];
    const float* fc2_w  = (const float*)d_in[12];
    const float* fc2_b  = (const float*)d_in[13];

    int N = in_sizes[0] / FIN;   // 20000
    int E = in_sizes[1] / 2;     // 640000
    int ball = N - 1;
    int EQ = (E + 3) / 4;

    k_pass1<<<8 + (EQ + 255) / 256, 256>>>(ei, E, ball, N, W1, a_src1, a_dst1);
    k_pass2<<<(EQ + 255) / 256, 256>>>(ei, E, N);
    k_agg1 <<<AGG_GRID, 256>>>(x, W1, b1, W2, a_src2, a_dst2,
                               b2, fc1_w, fc1_b, fc2_w, fc2_b,
                               (float*)d_out, ball);
}